// round 16
// baseline (speedup 1.0000x reference)
#include <cuda_runtime.h>
#include <cstdint>
#include <math.h>

// Problem constants
#define TT 256
#define NB 128
#define DD 1024
#define HH 1024
#define G4 4096                 // 4*H
#define NH (NB * HH)            // 131072

#define NCTAS 128               // persistent grid size (1 CTA/SM)

// recurrence smem (words): W slab 32x1024 (swizzled) + 2 halves x 3 stages x 128x32
#define W_WORDS   (32 * 1024)                    // 32768
#define STG_WORDS (128 * 32)                     // 4096
#define SEQ_WORDS (W_WORDS + 2 * 3 * STG_WORDS)  // 57344
#define SMEM_SEQ  (SEQ_WORDS * 4)                // 229376 B

// gemm: 256-thread CTAs, tile M128 x N64, warp tile m32n32, GS=2, 3 CTAs/SM
#define GS2 2
#define GEMM_SMEM (GS2 * (128 * 36 + 64 * 36) * 4)   // 55296 B

// XOR swizzle: permutes word-column bits [2:5) by row%8 -> conflict-free quads
#define SW(row, col) ((col) ^ (((row) & 7) << 2))

// ---------------- scratch (static device memory; no allocation) ----------------
__device__ float    g_Gx[(size_t)TT * NB * G4];   // [T*N, 4H] input projection + bias
__device__ float    g_H1[(size_t)TT * NB * HH];   // layer-0 hidden outputs (tf32 bits)
__device__ uint32_t g_xc[(size_t)TT * NB * DD];   // x pre-converted to tf32 bits
__device__ uint32_t g_Wihc[(size_t)2 * G4 * DD];  // W_ih pre-converted to tf32 bits
__device__ float    g_hA[NH];
__device__ float    g_hB[NH];
__device__ float    g_h0c[2 * NH];                // h0 pre-converted to tf32 bits

// grid barrier: monotonically increasing arrival counter (reset per layer by a kernel)
__device__ unsigned g_bar_arrive;

// ---------------- helpers ----------------
__device__ __forceinline__ uint32_t f2tf32(float x) {
    uint32_t r;
    asm("cvt.rna.tf32.f32 %0, %1;" : "=r"(r) : "f"(x));
    return r;
}

__device__ __forceinline__ void mma_tf32(float* d,
                                         uint32_t a0, uint32_t a1, uint32_t a2, uint32_t a3,
                                         uint32_t b0, uint32_t b1) {
    asm volatile(
        "mma.sync.aligned.m16n8k8.row.col.f32.tf32.tf32.f32 "
        "{%0,%1,%2,%3}, {%4,%5,%6,%7}, {%8,%9}, {%0,%1,%2,%3};\n"
        : "+f"(d[0]), "+f"(d[1]), "+f"(d[2]), "+f"(d[3])
        : "r"(a0), "r"(a1), "r"(a2), "r"(a3), "r"(b0), "r"(b1));
}

// MUFU-based fast activations (verified safe: rel_err delta ~3e-7)
__device__ __forceinline__ float fast_tanh(float x) {
    float r;
    asm("tanh.approx.f32 %0, %1;" : "=f"(r) : "f"(x));
    return r;
}
__device__ __forceinline__ float fast_sigm(float x) {
    return 0.5f * fast_tanh(0.5f * x) + 0.5f;
}

__device__ __forceinline__ void cpasync16(uint32_t* dst_smem, const void* src) {
    uint32_t a = (uint32_t)__cvta_generic_to_shared(dst_smem);
    asm volatile("cp.async.cg.shared.global [%0], [%1], 16;" :: "r"(a), "l"(src));
}
__device__ __forceinline__ void cp_commit() { asm volatile("cp.async.commit_group;"); }
template <int N>
__device__ __forceinline__ void cp_wait() { asm volatile("cp.async.wait_group %0;" :: "n"(N)); }

// fast grid barrier: REDG arrival + monotonic target polling
__device__ __forceinline__ void gsync_fast(unsigned* ctr, unsigned target) {
    __syncthreads();                 // CTA: h stores program-order complete
    if (threadIdx.x == 0) {
        __threadfence();             // make this CTA's writes globally visible
        asm volatile("red.relaxed.gpu.global.add.u32 [%0], 1;" :: "l"(ctr) : "memory");
        unsigned v;
        do {
            asm volatile("ld.relaxed.gpu.global.u32 %0, [%1];" : "=r"(v) : "l"(ctr));
        } while ((int)(v - target) < 0);
        __threadfence();             // acquire: order subsequent reads after observation
    }
    __syncthreads();
}

// ============================================================================
// Batched input projection, round-16: 256-thread CTAs, tile M128 x N64,
// warp tile m32 x n32 (acc = 32 regs), GS=2, __launch_bounds__(256,3)
// -> 24 warps/SM (6/SMSP) to cover LDS->HMMA latency.
// out[M,4096] = A[M,1024] @ W[4096,1024]^T + (b_ih+b_hh)
// ============================================================================
__global__ __launch_bounds__(256, 3) void gemm_gx2_kernel(
    const uint32_t* __restrict__ A,
    const uint32_t* __restrict__ W,
    const float* __restrict__ b_ih,
    const float* __restrict__ b_hh,
    float* __restrict__ out)
{
    extern __shared__ __align__(16) uint32_t gsm[];
    uint32_t* As = gsm;                         // [GS2][128][36]
    uint32_t* Ws = gsm + GS2 * 128 * 36;        // [GS2][64][36]

    const int tid  = threadIdx.x;
    const int lane = tid & 31;
    const int warp = tid >> 5;
    const int g    = lane >> 2;
    const int t4   = lane & 3;
    const int wm   = warp & 3;    // m offset wm*32
    const int wn   = warp >> 2;   // n offset wn*32

    const int n0 = blockIdx.x * 64;
    const int m0 = blockIdx.y * 128;

    const int ld_row = tid >> 3;  // 0..31
    const int ld_c4  = tid & 7;

    const uint32_t* Abase = A + (size_t)m0 * 1024 + ld_c4 * 4;
    const uint32_t* Wbase = W + (size_t)n0 * 1024 + ld_c4 * 4;

    auto load_stage = [&](int kt) {
        int s = kt & 1;
        uint32_t* Ad = As + s * (128 * 36);
        uint32_t* Wd = Ws + s * (64 * 36);
        const uint32_t* Asrc = Abase + kt * 32;
        const uint32_t* Wsrc = Wbase + kt * 32;
#pragma unroll
        for (int i = 0; i < 4; i++) {
            int row = ld_row + i * 32;
            cpasync16(&Ad[row * 36 + ld_c4 * 4], Asrc + (size_t)row * 1024);
        }
#pragma unroll
        for (int i = 0; i < 2; i++) {
            int row = ld_row + i * 32;
            cpasync16(&Wd[row * 36 + ld_c4 * 4], Wsrc + (size_t)row * 1024);
        }
        cp_commit();
    };

    float acc[2][4][4];   // [mi][ni][p] = 32 registers
#pragma unroll
    for (int mi = 0; mi < 2; mi++)
#pragma unroll
        for (int ni = 0; ni < 4; ni++)
#pragma unroll
            for (int p = 0; p < 4; p++) acc[mi][ni][p] = 0.0f;

    load_stage(0);
    load_stage(1);

    const int NK = 32;
    for (int kt = 0; kt < NK; kt++) {
        if (kt < NK - 1) { cp_wait<1>(); } else { cp_wait<0>(); }
        __syncthreads();

        const uint32_t* Ap = As + (kt & 1) * (128 * 36);
        const uint32_t* Wp = Ws + (kt & 1) * (64 * 36);

#pragma unroll
        for (int kk = 0; kk < 32; kk += 8) {
            uint32_t a[2][4];
#pragma unroll
            for (int mi = 0; mi < 2; mi++) {
                int r = wm * 32 + mi * 16;
                a[mi][0] = Ap[(r + g) * 36 + kk + t4];
                a[mi][1] = Ap[(r + g + 8) * 36 + kk + t4];
                a[mi][2] = Ap[(r + g) * 36 + kk + t4 + 4];
                a[mi][3] = Ap[(r + g + 8) * 36 + kk + t4 + 4];
            }
#pragma unroll
            for (int ni = 0; ni < 4; ni++) {
                int wr = wn * 32 + ni * 8 + g;
                uint32_t b0 = Wp[wr * 36 + kk + t4];
                uint32_t b1 = Wp[wr * 36 + kk + t4 + 4];
#pragma unroll
                for (int mi = 0; mi < 2; mi++)
                    mma_tf32(acc[mi][ni], a[mi][0], a[mi][1], a[mi][2], a[mi][3], b0, b1);
            }
        }

        __syncthreads();                       // stage kt&1 fully consumed
        if (kt + 2 < NK) load_stage(kt + 2);   // refill it
    }

#pragma unroll
    for (int mi = 0; mi < 2; mi++) {
#pragma unroll
        for (int ni = 0; ni < 4; ni++) {
            int row = m0 + wm * 32 + mi * 16 + g;
            int col = n0 + wn * 32 + ni * 8 + t4 * 2;
            float bias0 = b_ih[col] + b_hh[col];
            float bias1 = b_ih[col + 1] + b_hh[col + 1];
            out[(size_t)row * 4096 + col]           = acc[mi][ni][0] + bias0;
            out[(size_t)row * 4096 + col + 1]       = acc[mi][ni][1] + bias1;
            out[(size_t)(row + 8) * 4096 + col]     = acc[mi][ni][2] + bias0;
            out[(size_t)(row + 8) * 4096 + col + 1] = acc[mi][ni][3] + bias1;
        }
    }
}

// ============================================================================
// Persistent recurrence kernel = round-13 EXACTLY (best known: 8617 us).
// ============================================================================
__global__ __launch_bounds__(256) void lstm_seq_kernel(
    const float* __restrict__ Gx_base,   // [T, 128, 4096]
    const float* __restrict__ Whh,       // [4096, 1024] fp32 (this layer)
    const float* __restrict__ h0c,       // [128,1024] tf32 bits
    const float* __restrict__ c0l,       // [128,1024] fp32 (this layer)
    float* __restrict__ H1,              // mode0: output sequence (tf32 bits)
    float* __restrict__ hA, float* __restrict__ hB,  // mode1 ping-pong
    float* __restrict__ out,             // mode1: final fp32 [128,1024]
    int mode)
{
    extern __shared__ __align__(16) uint32_t sm[];
    uint32_t* ws = sm;                                  // [32][1024] swizzled

    const int tid  = threadIdx.x;
    const int lane = tid & 31;
    const int warp = tid >> 5;
    const int g    = lane >> 2;
    const int t4   = lane & 3;
    const int kw   = warp >> 2;   // 0,1: k half
    const int mw   = warp & 3;    // 0..3: 32-row m tile
    const int gx4  = g << 2;      // swizzle term for compute reads
    const int hu0  = blockIdx.x * 8;
    const int ht   = tid & 127;   // thread index within half
    const int toff = blockIdx.x & 15;   // per-CTA tile-order stagger

    unsigned* bar_ctr = &g_bar_arrive;

    // ---- load W slab once: 32 gate rows x 1024, cvt to tf32, swizzled ----
#pragma unroll
    for (int i = 0; i < 32; i++) {
        int idx4 = tid + i * 256;
        int row  = idx4 >> 8;            // 0..31
        int c4   = idx4 & 255;
        int grow = (row >> 3) * 1024 + hu0 + (row & 7);
        float4 v = *(const float4*)(Whh + (size_t)grow * 1024 + c4 * 4);
        uint4 u; u.x = f2tf32(v.x); u.y = f2tf32(v.y); u.z = f2tf32(v.z); u.w = f2tf32(v.w);
        *(uint4*)&ws[row * 1024 + SW(row, c4 * 4)] = u;
    }
    __syncthreads();

    // coalesced loader mapping (per half): 8 lanes cover one 128B line
    const int ld_row = ht >> 3;   // 0..15 (x8 iters -> 128 rows)
    const int ld_c4  = ht & 7;    // 16B chunk within the 32-col row

    // ---- c in registers: each half owns its own 2 row-groups ----
    float2 creg[2];
#pragma unroll
    for (int r2 = 0; r2 < 2; r2++) {
        int row = mw * 32 + g + (kw * 2 + r2) * 8;
        creg[r2] = __ldg((const float2*)(c0l + (size_t)row * 1024 + hu0 + t4 * 2));
    }

    for (int t = 0; t < TT; t++) {
        const uint32_t* hin;
        if (mode == 0)
            hin = (const uint32_t*)(t == 0 ? h0c : H1 + (size_t)(t - 1) * NH);
        else
            hin = (const uint32_t*)(t == 0 ? h0c : ((t & 1) ? hA : hB));

        // ---- Gx prefetch to registers (each half: its own 2 row-groups) ----
        const float* Gx = Gx_base + (size_t)t * NB * G4;
        float2 gxr[2][4];
#pragma unroll
        for (int r2 = 0; r2 < 2; r2++) {
            int row = mw * 32 + g + (kw * 2 + r2) * 8;
#pragma unroll
            for (int q = 0; q < 4; q++)
                gxr[r2][q] = __ldg((const float2*)(Gx + (size_t)row * 4096 +
                                                   q * 1024 + hu0 + t4 * 2));
        }

        // per-half staggered tile loader (phys tile index 0..15 within the half)
        auto load_tile = [&](int i) {
            int phys = (i + toff) & 15;
            uint32_t* dst = sm + W_WORDS + (kw * 3 + (i % 3)) * STG_WORDS;
            const uint32_t* src = hin + kw * 512 + phys * 32 + ld_c4 * 4;
#pragma unroll
            for (int j = 0; j < 8; j++) {
                int row = ld_row + j * 16;
                cpasync16(&dst[row * 32 + SW(row, ld_c4 * 4)], src + (size_t)row * 1024);
            }
            cp_commit();
        };

        float acc[2][4][4];   // [m-frag][gate][c]
#pragma unroll
        for (int mi = 0; mi < 2; mi++)
#pragma unroll
            for (int q = 0; q < 4; q++)
#pragma unroll
                for (int p = 0; p < 4; p++) acc[mi][q][p] = 0.0f;

        auto compute_tile = [&](int i) {
            int phys = (i + toff) & 15;
            const uint32_t* hp = sm + W_WORDS + (kw * 3 + (i % 3)) * STG_WORDS;
            const int kb = kw * 512 + phys * 32;
#pragma unroll
            for (int kk = 0; kk < 32; kk += 8) {
                const int ca = (kk + t4) ^ gx4;
                const int cb = (kk + t4 + 4) ^ gx4;
                uint32_t a[2][4];
#pragma unroll
                for (int mi = 0; mi < 2; mi++) {
                    int r = mw * 32 + mi * 16;
                    a[mi][0] = hp[(r + g) * 32 + ca];
                    a[mi][1] = hp[(r + g + 8) * 32 + ca];
                    a[mi][2] = hp[(r + g) * 32 + cb];
                    a[mi][3] = hp[(r + g + 8) * 32 + cb];
                }
#pragma unroll
                for (int q = 0; q < 4; q++) {
                    uint32_t b0 = ws[(q * 8 + g) * 1024 + ((kb + kk + t4) ^ gx4)];
                    uint32_t b1 = ws[(q * 8 + g) * 1024 + ((kb + kk + t4 + 4) ^ gx4)];
#pragma unroll
                    for (int mi = 0; mi < 2; mi++)
                        mma_tf32(acc[mi][q], a[mi][0], a[mi][1], a[mi][2], a[mi][3], b0, b1);
                }
            }
        };

        // half-pipeline: 16 tiles, 3 stages, named-barrier sync scoped to the half
        load_tile(0);
        load_tile(1);
#pragma unroll
        for (int i = 0; i < 16; i++) {
            if (i < 15) { cp_wait<1>(); } else { cp_wait<0>(); }
            asm volatile("bar.sync %0, 128;" :: "r"(kw + 1) : "memory");
            if (i + 2 < 16) load_tile(i + 2);
            compute_tile(i);
        }

        // ---- symmetric cross-k exchange: each half ships its PEER's mi ----
        __syncthreads();
        float* red = (float*)(sm + W_WORDS);
        auto xchg_write = [&](float (&a)[4][4]) {
            float* dst = red + (kw * 4 + mw) * 512;
#pragma unroll
            for (int q = 0; q < 4; q++)
#pragma unroll
                for (int p = 0; p < 4; p++)
                    dst[(q * 4 + p) * 32 + lane] = a[q][p];
        };
        auto xchg_add = [&](float (&a)[4][4]) {
            const float* srcr = red + ((1 - kw) * 4 + mw) * 512;
#pragma unroll
            for (int q = 0; q < 4; q++)
#pragma unroll
                for (int p = 0; p < 4; p++)
                    a[q][p] += srcr[(q * 4 + p) * 32 + lane];
        };
        auto epi = [&](float (&a)[4][4]) {
            uint32_t* hout = (uint32_t*)(mode == 0 ? (H1 + (size_t)t * NH)
                                                   : ((t & 1) ? hB : hA));
#pragma unroll
            for (int ph = 0; ph < 2; ph++) {
                int row = mw * 32 + g + (kw * 2 + ph) * 8;
                float hv[2];
#pragma unroll
                for (int uu = 0; uu < 2; uu++) {
                    int p = ph * 2 + uu;
                    float iv = a[0][p] + (uu ? gxr[ph][0].y : gxr[ph][0].x);
                    float fv = a[1][p] + (uu ? gxr[ph][1].y : gxr[ph][1].x);
                    float gv = a[2][p] + (uu ? gxr[ph][2].y : gxr[ph][2].x);
                    float ov = a[3][p] + (uu ? gxr[ph][3].y : gxr[ph][3].x);
                    float cold = uu ? creg[ph].y : creg[ph].x;
                    float cn = fast_sigm(fv) * cold + fast_sigm(iv) * fast_tanh(gv);
                    float hn = fast_sigm(ov) * fast_tanh(cn);
                    if (uu) creg[ph].y = cn; else creg[ph].x = cn;
                    hv[uu] = hn;
                }
                size_t idx = (size_t)row * 1024 + hu0 + t4 * 2;
                uint2 hw = make_uint2(f2tf32(hv[0]), f2tf32(hv[1]));
                *(uint2*)(hout + idx) = hw;
                if (mode == 1 && t == TT - 1)
                    *(float2*)(out + idx) = make_float2(hv[0], hv[1]);
            }
        };

        if (kw == 0) xchg_write(acc[1]); else xchg_write(acc[0]);
        __syncthreads();
        if (kw == 0) { xchg_add(acc[0]); epi(acc[0]); }
        else         { xchg_add(acc[1]); epi(acc[1]); }

        gsync_fast(bar_ctr, (unsigned)NCTAS * (unsigned)(t + 1));
    }
}

__global__ void bar_reset_kernel() { g_bar_arrive = 0; }

__global__ void cvt_tf32_kernel(const float* __restrict__ src, uint32_t* __restrict__ dst, int n) {
    int i = blockIdx.x * 256 + threadIdx.x;
    if (i < n) dst[i] = f2tf32(src[i]);
}

// ============================================================================
extern "C" void kernel_launch(void* const* d_in, const int* in_sizes, int n_in,
                              void* d_out, int out_size) {
    const float* x    = (const float*)d_in[0];
    const float* h0   = (const float*)d_in[1];
    const float* c0   = (const float*)d_in[2];
    const float* Wih  = (const float*)d_in[3];
    const float* Whh  = (const float*)d_in[4];
    const float* bih  = (const float*)d_in[5];
    const float* bhh  = (const float*)d_in[6];
    float* out = (float*)d_out;

    float *pGx, *pH1, *phA, *phB, *ph0c;
    uint32_t *pxc, *pWihc;
    cudaGetSymbolAddress((void**)&pGx,   g_Gx);
    cudaGetSymbolAddress((void**)&pH1,   g_H1);
    cudaGetSymbolAddress((void**)&phA,   g_hA);
    cudaGetSymbolAddress((void**)&phB,   g_hB);
    cudaGetSymbolAddress((void**)&ph0c,  g_h0c);
    cudaGetSymbolAddress((void**)&pxc,   g_xc);
    cudaGetSymbolAddress((void**)&pWihc, g_Wihc);

    static bool attr_set = false;
    if (!attr_set) {
        cudaFuncSetAttribute(lstm_seq_kernel,
                             cudaFuncAttributeMaxDynamicSharedMemorySize, SMEM_SEQ);
        cudaFuncSetAttribute(gemm_gx2_kernel,
                             cudaFuncAttributeMaxDynamicSharedMemorySize, GEMM_SMEM);
        attr_set = true;
    }

    const int M = TT * NB;  // 32768

    // one-time conversions: h0, x, W_ih -> tf32 bits
    cvt_tf32_kernel<<<(2 * NH) / 256, 256>>>(h0, (uint32_t*)ph0c, 2 * NH);
    cvt_tf32_kernel<<<(TT * NB * DD) / 256, 256>>>(x, pxc, TT * NB * DD);
    cvt_tf32_kernel<<<(2 * G4 * DD) / 256, 256>>>(Wih, pWihc, 2 * G4 * DD);

    for (int layer = 0; layer < 2; layer++) {
        const uint32_t* inp = (layer == 0) ? pxc : (const uint32_t*)pH1;
        const uint32_t* Wl  = pWihc + (size_t)layer * G4 * DD;
        const float*    Rl  = Whh + (size_t)layer * G4 * HH;

        dim3 grid_g(G4 / 64, M / 128);   // 64 x 256 CTAs of 256 threads
        gemm_gx2_kernel<<<grid_g, 256, GEMM_SMEM>>>(
            inp, Wl, bih + (size_t)layer * G4, bhh + (size_t)layer * G4, pGx);

        bar_reset_kernel<<<1, 1>>>();

        lstm_seq_kernel<<<NCTAS, 256, SMEM_SEQ>>>(
            pGx, Rl, ph0c + (size_t)layer * NH, c0 + (size_t)layer * NH,
            pH1, phA, phB, out, layer);
    }
}

// round 17
// speedup vs baseline: 1.0708x; 1.0708x over previous
#include <cuda_runtime.h>
#include <cstdint>
#include <math.h>

// Problem constants
#define TT 256
#define NB 128
#define DD 1024
#define HH 1024
#define G4 4096                 // 4*H
#define NH (NB * HH)            // 131072

#define NCTAS 128               // persistent grid size (1 CTA/SM)

// recurrence smem (words): W slab 32x1024 (swizzled) + 2 halves x 3 stages x 128x32
#define W_WORDS   (32 * 1024)                    // 32768
#define STG_WORDS (128 * 32)                     // 4096
#define SEQ_WORDS (W_WORDS + 2 * 3 * STG_WORDS)  // 57344
#define SMEM_SEQ  (SEQ_WORDS * 4)                // 229376 B

#define GS 3                    // gemm pipeline stages
#define GEMM_SMEM (GS * 128 * 36 * 2 * 4)   // 110592 B

// XOR swizzle: permutes word-column bits [2:5) by row%8 -> conflict-free quads
#define SW(row, col) ((col) ^ (((row) & 7) << 2))

// ---------------- scratch (static device memory; no allocation) ----------------
__device__ float    g_Gx[(size_t)TT * NB * G4];   // [T*N, 4H] input projection + bias
__device__ float    g_H1[(size_t)TT * NB * HH];   // layer-0 hidden outputs (tf32 bits)
__device__ uint32_t g_xc[(size_t)TT * NB * DD];   // x pre-converted to tf32 bits
__device__ uint32_t g_Wihc[(size_t)2 * G4 * DD];  // W_ih pre-converted to tf32 bits
__device__ float    g_hA[NH];
__device__ float    g_hB[NH];
__device__ float    g_h0c[2 * NH];                // h0 pre-converted to tf32 bits

// grid barrier: monotonically increasing arrival counter.
// Reset ONCE per kernel_launch invocation; layer l uses base l*NCTAS*TT.
__device__ unsigned g_bar_arrive;

// ---------------- helpers ----------------
__device__ __forceinline__ uint32_t f2tf32(float x) {
    uint32_t r;
    asm("cvt.rna.tf32.f32 %0, %1;" : "=r"(r) : "f"(x));
    return r;
}

__device__ __forceinline__ void mma_tf32(float* d,
                                         uint32_t a0, uint32_t a1, uint32_t a2, uint32_t a3,
                                         uint32_t b0, uint32_t b1) {
    asm volatile(
        "mma.sync.aligned.m16n8k8.row.col.f32.tf32.tf32.f32 "
        "{%0,%1,%2,%3}, {%4,%5,%6,%7}, {%8,%9}, {%0,%1,%2,%3};\n"
        : "+f"(d[0]), "+f"(d[1]), "+f"(d[2]), "+f"(d[3])
        : "r"(a0), "r"(a1), "r"(a2), "r"(a3), "r"(b0), "r"(b1));
}

// MUFU-based fast activations (verified safe: rel_err delta ~3e-7)
__device__ __forceinline__ float fast_tanh(float x) {
    float r;
    asm("tanh.approx.f32 %0, %1;" : "=f"(r) : "f"(x));
    return r;
}
__device__ __forceinline__ float fast_sigm(float x) {
    return 0.5f * fast_tanh(0.5f * x) + 0.5f;
}

__device__ __forceinline__ void cpasync16(uint32_t* dst_smem, const void* src) {
    uint32_t a = (uint32_t)__cvta_generic_to_shared(dst_smem);
    asm volatile("cp.async.cg.shared.global [%0], [%1], 16;" :: "r"(a), "l"(src));
}
__device__ __forceinline__ void cp_commit() { asm volatile("cp.async.commit_group;"); }
template <int N>
__device__ __forceinline__ void cp_wait() { asm volatile("cp.async.wait_group %0;" :: "n"(N)); }

// fast grid barrier: REDG arrival + monotonic target polling
__device__ __forceinline__ void gsync_fast(unsigned* ctr, unsigned target) {
    __syncthreads();                 // CTA: h stores program-order complete
    if (threadIdx.x == 0) {
        __threadfence();             // make this CTA's writes globally visible
        asm volatile("red.relaxed.gpu.global.add.u32 [%0], 1;" :: "l"(ctr) : "memory");
        unsigned v;
        do {
            asm volatile("ld.relaxed.gpu.global.u32 %0, [%1];" : "=r"(v) : "l"(ctr));
        } while ((int)(v - target) < 0);
        __threadfence();             // acquire: order subsequent reads after observation
    }
    __syncthreads();
}

// ============================================================================
// Pipelined batched input projection (round-13 config — the measured sweet
// spot: 128x128 tile, warp m32xn64, GS=3, 2 CTAs/SM, single sync per k-iter):
// out[M,4096] = A[M,1024] @ W[4096,1024]^T + (b_ih+b_hh)
// ============================================================================
__global__ __launch_bounds__(256, 2) void gemm_gx2_kernel(
    const uint32_t* __restrict__ A,
    const uint32_t* __restrict__ W,
    const float* __restrict__ b_ih,
    const float* __restrict__ b_hh,
    float* __restrict__ out)
{
    extern __shared__ __align__(16) uint32_t gsm[];
    uint32_t* As = gsm;
    uint32_t* Ws = gsm + GS * 128 * 36;

    const int tid  = threadIdx.x;
    const int lane = tid & 31;
    const int warp = tid >> 5;
    const int g    = lane >> 2;
    const int t4   = lane & 3;
    const int wm   = warp & 3;
    const int wn   = warp >> 2;

    const int n0 = blockIdx.x * 128;
    const int m0 = blockIdx.y * 128;

    const int ld_row = tid >> 3;
    const int ld_c4  = tid & 7;

    const uint32_t* Abase = A + (size_t)m0 * 1024 + ld_c4 * 4;
    const uint32_t* Wbase = W + (size_t)n0 * 1024 + ld_c4 * 4;

    auto load_stage = [&](int kt) {
        int s = kt % GS;
        uint32_t* Ad = As + s * (128 * 36);
        uint32_t* Wd = Ws + s * (128 * 36);
        const uint32_t* Asrc = Abase + kt * 32;
        const uint32_t* Wsrc = Wbase + kt * 32;
#pragma unroll
        for (int i = 0; i < 4; i++) {
            int row = ld_row + i * 32;
            cpasync16(&Ad[row * 36 + ld_c4 * 4], Asrc + (size_t)row * 1024);
            cpasync16(&Wd[row * 36 + ld_c4 * 4], Wsrc + (size_t)row * 1024);
        }
        cp_commit();
    };

    float acc[2][8][4];
#pragma unroll
    for (int mi = 0; mi < 2; mi++)
#pragma unroll
        for (int ni = 0; ni < 8; ni++)
#pragma unroll
            for (int p = 0; p < 4; p++) acc[mi][ni][p] = 0.0f;

    load_stage(0);
    load_stage(1);

    const int NK = 32;
    for (int kt = 0; kt < NK; kt++) {
        if (kt < NK - 1) { cp_wait<1>(); } else { cp_wait<0>(); }
        __syncthreads();
        if (kt + 2 < NK) load_stage(kt + 2);

        const uint32_t* Ap = As + (kt % GS) * (128 * 36);
        const uint32_t* Wp = Ws + (kt % GS) * (128 * 36);

#pragma unroll
        for (int kk = 0; kk < 32; kk += 8) {
            uint32_t a[2][4];
#pragma unroll
            for (int mi = 0; mi < 2; mi++) {
                int r = wm * 32 + mi * 16;
                a[mi][0] = Ap[(r + g) * 36 + kk + t4];
                a[mi][1] = Ap[(r + g + 8) * 36 + kk + t4];
                a[mi][2] = Ap[(r + g) * 36 + kk + t4 + 4];
                a[mi][3] = Ap[(r + g + 8) * 36 + kk + t4 + 4];
            }
#pragma unroll
            for (int ni = 0; ni < 8; ni++) {
                int wr = wn * 64 + ni * 8 + g;
                uint32_t b0 = Wp[wr * 36 + kk + t4];
                uint32_t b1 = Wp[wr * 36 + kk + t4 + 4];
#pragma unroll
                for (int mi = 0; mi < 2; mi++)
                    mma_tf32(acc[mi][ni], a[mi][0], a[mi][1], a[mi][2], a[mi][3], b0, b1);
            }
        }
    }

#pragma unroll
    for (int mi = 0; mi < 2; mi++) {
#pragma unroll
        for (int ni = 0; ni < 8; ni++) {
            int row = m0 + wm * 32 + mi * 16 + g;
            int col = n0 + wn * 64 + ni * 8 + t4 * 2;
            float bias0 = b_ih[col] + b_hh[col];
            float bias1 = b_ih[col + 1] + b_hh[col + 1];
            out[(size_t)row * 4096 + col]           = acc[mi][ni][0] + bias0;
            out[(size_t)row * 4096 + col + 1]       = acc[mi][ni][1] + bias1;
            out[(size_t)(row + 8) * 4096 + col]     = acc[mi][ni][2] + bias0;
            out[(size_t)(row + 8) * 4096 + col + 1] = acc[mi][ni][3] + bias1;
        }
    }
}

// ============================================================================
// Persistent recurrence kernel = round-13 (best known), with per-layer
// monotonic barrier base (counter reset once per invocation, not per layer).
// ============================================================================
__global__ __launch_bounds__(256) void lstm_seq_kernel(
    const float* __restrict__ Gx_base,   // [T, 128, 4096]
    const float* __restrict__ Whh,       // [4096, 1024] fp32 (this layer)
    const float* __restrict__ h0c,       // [128,1024] tf32 bits
    const float* __restrict__ c0l,       // [128,1024] fp32 (this layer)
    float* __restrict__ H1,              // mode0: output sequence (tf32 bits)
    float* __restrict__ hA, float* __restrict__ hB,  // mode1 ping-pong
    float* __restrict__ out,             // mode1: final fp32 [128,1024]
    int mode, unsigned bar_base)
{
    extern __shared__ __align__(16) uint32_t sm[];
    uint32_t* ws = sm;                                  // [32][1024] swizzled

    const int tid  = threadIdx.x;
    const int lane = tid & 31;
    const int warp = tid >> 5;
    const int g    = lane >> 2;
    const int t4   = lane & 3;
    const int kw   = warp >> 2;   // 0,1: k half
    const int mw   = warp & 3;    // 0..3: 32-row m tile
    const int gx4  = g << 2;      // swizzle term for compute reads
    const int hu0  = blockIdx.x * 8;
    const int ht   = tid & 127;   // thread index within half
    const int toff = blockIdx.x & 15;   // per-CTA tile-order stagger

    unsigned* bar_ctr = &g_bar_arrive;

    // ---- load W slab once: 32 gate rows x 1024, cvt to tf32, swizzled ----
#pragma unroll
    for (int i = 0; i < 32; i++) {
        int idx4 = tid + i * 256;
        int row  = idx4 >> 8;            // 0..31
        int c4   = idx4 & 255;
        int grow = (row >> 3) * 1024 + hu0 + (row & 7);
        float4 v = *(const float4*)(Whh + (size_t)grow * 1024 + c4 * 4);
        uint4 u; u.x = f2tf32(v.x); u.y = f2tf32(v.y); u.z = f2tf32(v.z); u.w = f2tf32(v.w);
        *(uint4*)&ws[row * 1024 + SW(row, c4 * 4)] = u;
    }
    __syncthreads();

    // coalesced loader mapping (per half): 8 lanes cover one 128B line
    const int ld_row = ht >> 3;   // 0..15 (x8 iters -> 128 rows)
    const int ld_c4  = ht & 7;    // 16B chunk within the 32-col row

    // ---- c in registers: each half owns its own 2 row-groups ----
    float2 creg[2];
#pragma unroll
    for (int r2 = 0; r2 < 2; r2++) {
        int row = mw * 32 + g + (kw * 2 + r2) * 8;
        creg[r2] = __ldg((const float2*)(c0l + (size_t)row * 1024 + hu0 + t4 * 2));
    }

    for (int t = 0; t < TT; t++) {
        const uint32_t* hin;
        if (mode == 0)
            hin = (const uint32_t*)(t == 0 ? h0c : H1 + (size_t)(t - 1) * NH);
        else
            hin = (const uint32_t*)(t == 0 ? h0c : ((t & 1) ? hA : hB));

        // ---- Gx prefetch to registers (each half: its own 2 row-groups) ----
        const float* Gx = Gx_base + (size_t)t * NB * G4;
        float2 gxr[2][4];
#pragma unroll
        for (int r2 = 0; r2 < 2; r2++) {
            int row = mw * 32 + g + (kw * 2 + r2) * 8;
#pragma unroll
            for (int q = 0; q < 4; q++)
                gxr[r2][q] = __ldg((const float2*)(Gx + (size_t)row * 4096 +
                                                   q * 1024 + hu0 + t4 * 2));
        }

        // per-half staggered tile loader (phys tile index 0..15 within the half)
        auto load_tile = [&](int i) {
            int phys = (i + toff) & 15;
            uint32_t* dst = sm + W_WORDS + (kw * 3 + (i % 3)) * STG_WORDS;
            const uint32_t* src = hin + kw * 512 + phys * 32 + ld_c4 * 4;
#pragma unroll
            for (int j = 0; j < 8; j++) {
                int row = ld_row + j * 16;
                cpasync16(&dst[row * 32 + SW(row, ld_c4 * 4)], src + (size_t)row * 1024);
            }
            cp_commit();
        };

        float acc[2][4][4];   // [m-frag][gate][c]
#pragma unroll
        for (int mi = 0; mi < 2; mi++)
#pragma unroll
            for (int q = 0; q < 4; q++)
#pragma unroll
                for (int p = 0; p < 4; p++) acc[mi][q][p] = 0.0f;

        auto compute_tile = [&](int i) {
            int phys = (i + toff) & 15;
            const uint32_t* hp = sm + W_WORDS + (kw * 3 + (i % 3)) * STG_WORDS;
            const int kb = kw * 512 + phys * 32;
#pragma unroll
            for (int kk = 0; kk < 32; kk += 8) {
                const int ca = (kk + t4) ^ gx4;
                const int cb = (kk + t4 + 4) ^ gx4;
                uint32_t a[2][4];
#pragma unroll
                for (int mi = 0; mi < 2; mi++) {
                    int r = mw * 32 + mi * 16;
                    a[mi][0] = hp[(r + g) * 32 + ca];
                    a[mi][1] = hp[(r + g + 8) * 32 + ca];
                    a[mi][2] = hp[(r + g) * 32 + cb];
                    a[mi][3] = hp[(r + g + 8) * 32 + cb];
                }
#pragma unroll
                for (int q = 0; q < 4; q++) {
                    uint32_t b0 = ws[(q * 8 + g) * 1024 + ((kb + kk + t4) ^ gx4)];
                    uint32_t b1 = ws[(q * 8 + g) * 1024 + ((kb + kk + t4 + 4) ^ gx4)];
#pragma unroll
                    for (int mi = 0; mi < 2; mi++)
                        mma_tf32(acc[mi][q], a[mi][0], a[mi][1], a[mi][2], a[mi][3], b0, b1);
                }
            }
        };

        // half-pipeline: 16 tiles, 3 stages, named-barrier sync scoped to the half
        load_tile(0);
        load_tile(1);
#pragma unroll
        for (int i = 0; i < 16; i++) {
            if (i < 15) { cp_wait<1>(); } else { cp_wait<0>(); }
            asm volatile("bar.sync %0, 128;" :: "r"(kw + 1) : "memory");
            if (i + 2 < 16) load_tile(i + 2);
            compute_tile(i);
        }

        // ---- symmetric cross-k exchange: each half ships its PEER's mi ----
        __syncthreads();
        float* red = (float*)(sm + W_WORDS);
        auto xchg_write = [&](float (&a)[4][4]) {
            float* dst = red + (kw * 4 + mw) * 512;
#pragma unroll
            for (int q = 0; q < 4; q++)
#pragma unroll
                for (int p = 0; p < 4; p++)
                    dst[(q * 4 + p) * 32 + lane] = a[q][p];
        };
        auto xchg_add = [&](float (&a)[4][4]) {
            const float* srcr = red + ((1 - kw) * 4 + mw) * 512;
#pragma unroll
            for (int q = 0; q < 4; q++)
#pragma unroll
                for (int p = 0; p < 4; p++)
                    a[q][p] += srcr[(q * 4 + p) * 32 + lane];
        };
        auto epi = [&](float (&a)[4][4]) {
            uint32_t* hout = (uint32_t*)(mode == 0 ? (H1 + (size_t)t * NH)
                                                   : ((t & 1) ? hB : hA));
#pragma unroll
            for (int ph = 0; ph < 2; ph++) {
                int row = mw * 32 + g + (kw * 2 + ph) * 8;
                float hv[2];
#pragma unroll
                for (int uu = 0; uu < 2; uu++) {
                    int p = ph * 2 + uu;
                    float iv = a[0][p] + (uu ? gxr[ph][0].y : gxr[ph][0].x);
                    float fv = a[1][p] + (uu ? gxr[ph][1].y : gxr[ph][1].x);
                    float gv = a[2][p] + (uu ? gxr[ph][2].y : gxr[ph][2].x);
                    float ov = a[3][p] + (uu ? gxr[ph][3].y : gxr[ph][3].x);
                    float cold = uu ? creg[ph].y : creg[ph].x;
                    float cn = fast_sigm(fv) * cold + fast_sigm(iv) * fast_tanh(gv);
                    float hn = fast_sigm(ov) * fast_tanh(cn);
                    if (uu) creg[ph].y = cn; else creg[ph].x = cn;
                    hv[uu] = hn;
                }
                size_t idx = (size_t)row * 1024 + hu0 + t4 * 2;
                uint2 hw = make_uint2(f2tf32(hv[0]), f2tf32(hv[1]));
                *(uint2*)(hout + idx) = hw;
                if (mode == 1 && t == TT - 1)
                    *(float2*)(out + idx) = make_float2(hv[0], hv[1]);
            }
        };

        if (kw == 0) xchg_write(acc[1]); else xchg_write(acc[0]);
        __syncthreads();
        if (kw == 0) { xchg_add(acc[0]); epi(acc[0]); }
        else         { xchg_add(acc[1]); epi(acc[1]); }

        gsync_fast(bar_ctr, bar_base + (unsigned)NCTAS * (unsigned)(t + 1));
    }
}

__global__ void bar_reset_kernel() { g_bar_arrive = 0; }

__global__ void cvt_tf32_kernel(const float* __restrict__ src, uint32_t* __restrict__ dst, int n) {
    int i = blockIdx.x * 256 + threadIdx.x;
    if (i < n) dst[i] = f2tf32(src[i]);
}

// ============================================================================
extern "C" void kernel_launch(void* const* d_in, const int* in_sizes, int n_in,
                              void* d_out, int out_size) {
    const float* x    = (const float*)d_in[0];
    const float* h0   = (const float*)d_in[1];
    const float* c0   = (const float*)d_in[2];
    const float* Wih  = (const float*)d_in[3];
    const float* Whh  = (const float*)d_in[4];
    const float* bih  = (const float*)d_in[5];
    const float* bhh  = (const float*)d_in[6];
    float* out = (float*)d_out;

    float *pGx, *pH1, *phA, *phB, *ph0c;
    uint32_t *pxc, *pWihc;
    cudaGetSymbolAddress((void**)&pGx,   g_Gx);
    cudaGetSymbolAddress((void**)&pH1,   g_H1);
    cudaGetSymbolAddress((void**)&phA,   g_hA);
    cudaGetSymbolAddress((void**)&phB,   g_hB);
    cudaGetSymbolAddress((void**)&ph0c,  g_h0c);
    cudaGetSymbolAddress((void**)&pxc,   g_xc);
    cudaGetSymbolAddress((void**)&pWihc, g_Wihc);

    static bool attr_set = false;
    if (!attr_set) {
        cudaFuncSetAttribute(lstm_seq_kernel,
                             cudaFuncAttributeMaxDynamicSharedMemorySize, SMEM_SEQ);
        cudaFuncSetAttribute(gemm_gx2_kernel,
                             cudaFuncAttributeMaxDynamicSharedMemorySize, GEMM_SMEM);
        attr_set = true;
    }

    const int M = TT * NB;  // 32768

    // once per invocation: reset barrier counter; one-time tf32 conversions
    bar_reset_kernel<<<1, 1>>>();
    cvt_tf32_kernel<<<(2 * NH) / 256, 256>>>(h0, (uint32_t*)ph0c, 2 * NH);
    cvt_tf32_kernel<<<(TT * NB * DD) / 256, 256>>>(x, pxc, TT * NB * DD);
    cvt_tf32_kernel<<<(2 * G4 * DD) / 256, 256>>>(Wih, pWihc, 2 * G4 * DD);

    for (int layer = 0; layer < 2; layer++) {
        const uint32_t* inp = (layer == 0) ? pxc : (const uint32_t*)pH1;
        const uint32_t* Wl  = pWihc + (size_t)layer * G4 * DD;
        const float*    Rl  = Whh + (size_t)layer * G4 * HH;

        dim3 grid_g(G4 / 128, M / 128);
        gemm_gx2_kernel<<<grid_g, 256, GEMM_SMEM>>>(
            inp, Wl, bih + (size_t)layer * G4, bhh + (size_t)layer * G4, pGx);

        lstm_seq_kernel<<<NCTAS, 256, SMEM_SEQ>>>(
            pGx, Rl, ph0c + (size_t)layer * NH, c0 + (size_t)layer * NH,
            pH1, phA, phB, out, layer,
            (unsigned)layer * (unsigned)NCTAS * (unsigned)TT);
    }
}